// round 8
// baseline (speedup 1.0000x reference)
#include <cuda_runtime.h>

#define BB    8
#define NMAX  128
#define HH    192
#define WW    256
#define INV_DOWN 0.125f
#define NBOX   (BB * NMAX)        // 1024 boxes
#define GROUPS 4                  // boxes per CTA
#define GRIDB  (NBOX / GROUPS)    // 256 CTAs
#define GTHR   128                // threads per group

// Antiderivative of the bilinear hat kernel, clipped to [-1, 1] (branchless)
__device__ __forceinline__ float hatP(float u) {
    u = fminf(1.0f, fmaxf(-1.0f, u));
    float neg = 0.5f * (u + 1.0f) * (u + 1.0f);
    float pos = 0.5f + u - 0.5f * u * u;
    return (u <= 0.0f) ? neg : pos;
}

// Group-scoped barrier: named barrier `id`, 128 threads participate.
__device__ __forceinline__ void group_sync(int id) {
    asm volatile("bar.sync %0, %1;" :: "r"(id), "r"(GTHR) : "memory");
}

__global__ __launch_bounds__(GROUPS * GTHR)
void count_kernel(const float* __restrict__ den,     // [B, 1, H, W]
                  const float* __restrict__ hboxes,  // [B, NMAX, 5]
                  const float* __restrict__ post,    // [B, NMAX, H, W]
                  float* __restrict__ out)           // zeroed by memset node
{
    const int g    = threadIdx.x >> 7;         // group 0..3
    const int t    = threadIdx.x & (GTHR - 1); // lane within group
    const int w    = t >> 5;                   // warp within group
    const int lane = t & 31;
    const int bn   = blockIdx.x * GROUPS + g;  // this group's box
    const int b    = bn >> 7;                  // image index

    const float* box = hboxes + (size_t)bn * 5;
    const float lab = __ldg(box + 4);
    if (lab <= 0.0f) return;                   // whole group exits (barrier is group-private)

    __shared__ int   s_cnt[GROUPS][4];
    __shared__ float s_sum[GROUPS][4];

    // num_b: 128 threads of this group -> one label each (L2-hot).
    const float myLab = __ldg(hboxes + (size_t)b * NMAX * 5 + t * 5 + 4);
    const unsigned bal = __ballot_sync(0xffffffffu, myLab > 0.0f);
    if (lane == 0) s_cnt[g][w] = __popc(bal);

    // Box geometry, weights computed inline per cell (registers only).
    const float x1 = __ldg(box + 0) * INV_DOWN;
    const float y1 = __ldg(box + 1) * INV_DOWN;
    const float x2 = __ldg(box + 2) * INV_DOWN;
    const float y2 = __ldg(box + 3) * INV_DOWN;

    const int ix0 = max(0, (int)floorf(x1) - 1);
    const int ix1 = min(WW - 1, (int)ceilf(x2) + 1);
    const int iy0 = max(0, (int)floorf(y1) - 1);
    const int iy1 = min(HH - 1, (int)ceilf(y2) + 1);
    const int nx = ix1 - ix0 + 1;      // <= ~24
    const int ny = iy1 - iy0 + 1;      // <= ~24
    const int total = nx * ny;         // <= ~576

    // Magic divide: jy = k / nx via umulhi, exact for k < 2^16.
    const unsigned magic = (unsigned)(((1ull << 32) + (unsigned)nx - 1) / (unsigned)nx);

    const float* denB  = den  + (size_t)b  * (HH * WW);
    const float* postN = post + (size_t)bn * (HH * WW);

    float acc = 0.0f;
    #pragma unroll 4
    for (int k = t; k < total; k += GTHR) {
        const int jy = (int)__umulhi((unsigned)k, magic);
        const int jx = k - jy * nx;
        const int x  = ix0 + jx;
        const int y  = iy0 + jy;
        const int idx = y * WW + x;
        const float d = __ldg(denB  + idx);
        const float p = __ldg(postN + idx);
        const float wxv = hatP(x2 - (float)x) - hatP(x1 - (float)x);
        const float wyv = hatP(y2 - (float)y) - hatP(y1 - (float)y);
        acc += (wxv * wyv) * (d * p);
    }

    // Warp reduce -> smem -> group barrier -> group leader finalizes box.
    #pragma unroll
    for (int o = 16; o > 0; o >>= 1)
        acc += __shfl_down_sync(0xffffffffu, acc, o);
    if (lane == 0) s_sum[g][w] = acc;
    group_sync(g);

    if (t == 0) {
        const float count = s_sum[g][0] + s_sum[g][1] + s_sum[g][2] + s_sum[g][3];
        const int   num   = s_cnt[g][0] + s_cnt[g][1] + s_cnt[g][2] + s_cnt[g][3];
        // per_img = sum_i |c_i - 1| / num_b, division distributed per box.
        atomicAdd(out, fabsf(count - 1.0f) * (1.0f / (float)num));
    }
}

extern "C" void kernel_launch(void* const* d_in, const int* in_sizes, int n_in,
                              void* d_out, int out_size)
{
    // metadata order: cls(0), reg(1), off(2), den(3), fboxes(4), hboxes(5),
    //                 ctr_masks(6), post_probs(7)
    const float* den    = (const float*)d_in[3];
    const float* hboxes = (const float*)d_in[5];
    const float* post   = (const float*)d_in[7];
    float* out = (float*)d_out;

    cudaMemsetAsync(out, 0, sizeof(float));          // graph memset node
    count_kernel<<<GRIDB, GROUPS * GTHR>>>(den, hboxes, post, out);
}

// round 9
// speedup vs baseline: 1.1103x; 1.1103x over previous
#include <cuda_runtime.h>

#define BB    8
#define NMAX  128
#define HH    192
#define WW    256
#define INV_DOWN 0.125f
#define NBOX  (BB * NMAX)   // 1024 blocks, one per box

__device__ float        g_acc   = 0.0f;  // self-resetting accumulator
__device__ unsigned int g_count = 0;     // arrival counter (self-resetting)

// Antiderivative of the bilinear hat kernel, clipped to [-1, 1] (branchless)
__device__ __forceinline__ float hatP(float u) {
    u = fminf(1.0f, fmaxf(-1.0f, u));
    float neg = 0.5f * (u + 1.0f) * (u + 1.0f);
    float pos = 0.5f + u - 0.5f * u * u;
    return (u <= 0.0f) ? neg : pos;
}

// Arrival with acq_rel ordering: no CCTL.IVALL L1 flush (unlike __threadfence).
__device__ __forceinline__ unsigned arrive_acq_rel(unsigned* addr) {
    unsigned old;
    asm volatile("atom.add.acq_rel.gpu.global.u32 %0, [%1], %2;"
                 : "=r"(old) : "l"(addr), "r"(1u) : "memory");
    return old;
}

__global__ __launch_bounds__(128)
void count_kernel(const float* __restrict__ den,     // [B, 1, H, W]
                  const float* __restrict__ hboxes,  // [B, NMAX, 5]
                  const float* __restrict__ post,    // [B, NMAX, H, W]
                  float* __restrict__ out)
{
    const int bn = blockIdx.x;
    const int b  = bn >> 7;            // bn / NMAX
    const int t  = threadIdx.x;
    const int w  = t >> 5;
    const int lane = t & 31;

    const float* box = hboxes + (size_t)bn * 5;
    const float lab = __ldg(box + 4);

    if (lab > 0.0f) {
        __shared__ int   s_cnt[4];
        __shared__ float s_sum[4];

        // num_b: 128 threads -> one label each (L2-hot).
        const float myLab = __ldg(hboxes + (size_t)b * NMAX * 5 + t * 5 + 4);
        const unsigned bal = __ballot_sync(0xffffffffu, myLab > 0.0f);
        if (lane == 0) s_cnt[w] = __popc(bal);

        // Box geometry; weights computed inline per cell (registers only).
        const float x1 = __ldg(box + 0) * INV_DOWN;
        const float y1 = __ldg(box + 1) * INV_DOWN;
        const float x2 = __ldg(box + 2) * INV_DOWN;
        const float y2 = __ldg(box + 3) * INV_DOWN;

        const int ix0 = max(0, (int)floorf(x1) - 1);
        const int ix1 = min(WW - 1, (int)ceilf(x2) + 1);
        const int iy0 = max(0, (int)floorf(y1) - 1);
        const int iy1 = min(HH - 1, (int)ceilf(y2) + 1);
        const int nx = ix1 - ix0 + 1;      // <= ~24
        const int ny = iy1 - iy0 + 1;      // <= ~24
        const int total = nx * ny;         // <= ~576

        // Magic divide: jy = k / nx via umulhi, exact for k < 2^16.
        const unsigned magic =
            (unsigned)(((1ull << 32) + (unsigned)nx - 1) / (unsigned)nx);

        const float* denB  = den  + (size_t)b  * (HH * WW);
        const float* postN = post + (size_t)bn * (HH * WW);

        float acc = 0.0f;
        #pragma unroll 4
        for (int k = t; k < total; k += 128) {
            const int jy = (int)__umulhi((unsigned)k, magic);
            const int jx = k - jy * nx;
            const int x  = ix0 + jx;
            const int y  = iy0 + jy;
            const int idx = y * WW + x;
            const float d = __ldg(denB  + idx);
            const float p = __ldg(postN + idx);
            const float wxv = hatP(x2 - (float)x) - hatP(x1 - (float)x);
            const float wyv = hatP(y2 - (float)y) - hatP(y1 - (float)y);
            acc += (wxv * wyv) * (d * p);
        }

        #pragma unroll
        for (int o = 16; o > 0; o >>= 1)
            acc += __shfl_down_sync(0xffffffffu, acc, o);
        if (lane == 0) s_sum[w] = acc;
        __syncthreads();

        if (t == 0) {
            const float count = s_sum[0] + s_sum[1] + s_sum[2] + s_sum[3];
            const int   num   = s_cnt[0] + s_cnt[1] + s_cnt[2] + s_cnt[3];
            // per_img = sum_i |c_i - 1| / num_b, division distributed per box.
            atomicAdd(&g_acc, fabsf(count - 1.0f) * (1.0f / (float)num));
        }
    }

    // Every block arrives; the last one publishes + resets (single-node graph,
    // no memset node needed).
    if (t == 0) {
        if (arrive_acq_rel(&g_count) == (unsigned)(NBOX - 1)) {
            const float tot = atomicExch(&g_acc, 0.0f);  // read + reset, L2 atomic
            out[0] = tot;
            atomicExch(&g_count, 0u);                    // reset for next replay
        }
    }
}

extern "C" void kernel_launch(void* const* d_in, const int* in_sizes, int n_in,
                              void* d_out, int out_size)
{
    // metadata order: cls(0), reg(1), off(2), den(3), fboxes(4), hboxes(5),
    //                 ctr_masks(6), post_probs(7)
    const float* den    = (const float*)d_in[3];
    const float* hboxes = (const float*)d_in[5];
    const float* post   = (const float*)d_in[7];
    float* out = (float*)d_out;

    count_kernel<<<NBOX, 128>>>(den, hboxes, post, out);
}